// round 13
// baseline (speedup 1.0000x reference)
#include <cuda_runtime.h>
#include <cuda_fp16.h>
#include <cstdint>

#define Hd 512
#define Bn 8
#define Sn 128
#define Mn 32
#define Nn 64

#define ROWS_Y  (Bn * (Sn - 1) * Nn)   // 65024 = 508*128
#define ROWS_X  (Bn * Sn * Mn)         // 32768 = 256*128
#define NSLICE  16

// ---------------- device scratch ----------------
__device__ float g_spart[NSLICE * ROWS_X];
__device__ float g_pooled[Bn * Sn * Hd];
__device__ float g_ci[Bn * (Sn - 1) * Hd];

__device__ __half g_x16[(size_t)ROWS_X * Hd];
__device__ __half g_y16[(size_t)ROWS_Y * Hd];
__device__ __half g_p16[(size_t)(Bn * Sn) * Hd];   // pooled fp16, row = b*128+s
__device__ __half g_bs16[Hd * Hd];   // scores B: fp16(Wa1^T) [g][k]
__device__ __half g_bm16[Hd * Hd];   // main B: fp16(Wy rows) [g][k]
__device__ __half g_bi16[Hd * Hd];   // ci B: fp16(Wi rows) [g][k]

// ---------------- helpers ----------------
__device__ __forceinline__ uint32_t smem_u32(const void* p) {
    uint32_t a;
    asm("{ .reg .u64 t; cvta.to.shared.u64 t, %1; cvt.u32.u64 %0, t; }" : "=r"(a) : "l"(p));
    return a;
}
__device__ __forceinline__ void cp16(uint32_t saddr, const void* gptr) {
    asm volatile("cp.async.cg.shared.global [%0], [%1], 16;" :: "r"(saddr), "l"(gptr));
}
__device__ __forceinline__ void ldsm4(uint32_t* r, uint32_t addr) {
    asm volatile("ldmatrix.sync.aligned.m8n8.x4.shared.b16 {%0,%1,%2,%3}, [%4];"
                 : "=r"(r[0]), "=r"(r[1]), "=r"(r[2]), "=r"(r[3]) : "r"(addr));
}
__device__ __forceinline__ void mma_h(float* c, const uint32_t* a, const uint32_t* b) {
    asm volatile(
        "mma.sync.aligned.m16n8k16.row.col.f32.f16.f16.f32 "
        "{%0,%1,%2,%3}, {%4,%5,%6,%7}, {%8,%9}, {%0,%1,%2,%3};"
        : "+f"(c[0]), "+f"(c[1]), "+f"(c[2]), "+f"(c[3])
        : "r"(a[0]), "r"(a[1]), "r"(a[2]), "r"(a[3]), "r"(b[0]), "r"(b[1]));
}
__device__ __forceinline__ float tanh_fast(float x) {
    float r;
    asm("tanh.approx.f32 %0, %1;" : "=f"(r) : "f"(x));
    return r;
}
// gate = sigmoid(x) = 0.5 + 0.5*tanh(0.5x)  (1 MUFU)
__device__ __forceinline__ float fsig(float x) {
    return fmaf(tanh_fast(0.5f * x), 0.5f, 0.5f);
}

__device__ __forceinline__ unsigned pkh(float a, float b) {
    __half2 t = __floats2half2_rn(a, b);
    return *reinterpret_cast<unsigned*>(&t);
}

// swizzled offset inside a [rows x 64 fp16] tile (128 B rows)
__device__ __forceinline__ uint32_t sw(int row, int c8) {
    return (uint32_t)(row * 128 + ((c8 ^ (row & 7)) << 4));
}

// ============================================================================
// k_cvt_xw: blocks [0, 32768) convert x; [32768, 33280) convert weights
// ============================================================================
__global__ __launch_bounds__(128) void k_cvt_xw(const float* __restrict__ x,
                                                const float* __restrict__ Wa1,
                                                const float* __restrict__ Wl) {
    const int t = threadIdx.x;
    if (blockIdx.x < 32768) {
        const int r = blockIdx.x;
        float4 v = *(const float4*)(x + ((size_t)r << 9) + t * 4);
        uint2 h;
        h.x = pkh(v.x, v.y); h.y = pkh(v.z, v.w);
        ((uint2*)g_x16)[(size_t)r * 128 + t] = h;
    } else {
        const int g = blockIdx.x - 32768;
        {   // main B: Wl row g, first Hd cols (Wy)
            float4 v = *(const float4*)(Wl + (size_t)g * 1024 + t * 4);
            uint2 h;
            h.x = pkh(v.x, v.y); h.y = pkh(v.z, v.w);
            ((uint2*)g_bm16)[(size_t)g * 128 + t] = h;
        }
        {   // ci B: Wl row g, cols [Hd, 2Hd) (Wi)
            float4 v = *(const float4*)(Wl + (size_t)g * 1024 + Hd + t * 4);
            uint2 h;
            h.x = pkh(v.x, v.y); h.y = pkh(v.z, v.w);
            ((uint2*)g_bi16)[(size_t)g * 128 + t] = h;
        }
        {   // scores B: Wa1^T row g
            int k0 = t * 4;
            float a = Wa1[(size_t)(k0 + 0) * Hd + g];
            float b = Wa1[(size_t)(k0 + 1) * Hd + g];
            float c = Wa1[(size_t)(k0 + 2) * Hd + g];
            float d = Wa1[(size_t)(k0 + 3) * Hd + g];
            uint2 h;
            h.x = pkh(a, b); h.y = pkh(c, d);
            ((uint2*)g_bs16)[(size_t)g * 128 + t] = h;
        }
    }
}

// ============================================================================
// 3-stage pipelined fp16 mainloop: block tile 128(M) x 128(N), K=512.
// Stage: A 16K | B 16K = 32 KB; 3 stages (96 KB/CTA), 2 CTAs/SM.
// 256 threads, warps 2(M) x 4(N), warp tile 64x32, fp32 accumulate.
// ============================================================================
#define STG   32768
#define DSMEM (3 * STG + 128)

__device__ __forceinline__ void hmma_loop3(
    const __half* __restrict__ A16, const __half* __restrict__ B16,
    uint32_t smu, float acc[4][4][4])
{
    const int tid = threadIdx.x;
    const int lid = tid & 31, wid = tid >> 5;
    const int wm = wid >> 2, wn = wid & 3;

    int rowS[4], c8S[4];
    uint32_t soS[4];
#pragma unroll
    for (int i = 0; i < 4; i++) {
        int id = tid + 256 * i;
        rowS[i] = id >> 3; c8S[i] = id & 7;
        soS[i] = sw(rowS[i], c8S[i]);
    }

    const int rowA_base = wm * 64 + (lid & 15);
    const int c8A_half = lid >> 4;
    const int rowB_base = wn * 32 + ((lid >> 4) << 3) + (lid & 7);
    const int c8B_half = (lid >> 3) & 1;

    // prologue: chunks 0 and 1
#pragma unroll
    for (int p = 0; p < 2; p++) {
        const uint32_t bb = smu + p * STG;
        const int kk = p * 64;
#pragma unroll
        for (int i = 0; i < 4; i++) {
            const size_t go = (size_t)rowS[i] * Hd + kk + c8S[i] * 8;
            cp16(bb + soS[i], A16 + go);
            cp16(bb + 16384 + soS[i], B16 + go);
        }
        asm volatile("cp.async.commit_group;");
    }

#pragma unroll
    for (int it = 0; it < 8; ++it) {
        if (it == 7) asm volatile("cp.async.wait_group 0;" ::: "memory");
        else         asm volatile("cp.async.wait_group 1;" ::: "memory");
        __syncthreads();

        if (it < 6) {
            const uint32_t bb = smu + ((it + 2) % 3) * STG;
            const int kk = (it + 2) * 64;
#pragma unroll
            for (int i = 0; i < 4; i++) {
                const size_t go = (size_t)rowS[i] * Hd + kk + c8S[i] * 8;
                cp16(bb + soS[i], A16 + go);
                cp16(bb + 16384 + soS[i], B16 + go);
            }
            asm volatile("cp.async.commit_group;");
        }

        const uint32_t b0 = smu + (it % 3) * STG;
#pragma unroll
        for (int ks = 0; ks < 4; ks++) {
            uint32_t bh[8];
#pragma unroll
            for (int q = 0; q < 2; q++) {
                uint32_t off = sw(rowB_base + q * 16, ks * 2 + c8B_half);
                ldsm4(&bh[q * 4], b0 + 16384 + off);
            }
#pragma unroll
            for (int mf = 0; mf < 4; mf++) {
                uint32_t off = sw(rowA_base + mf * 16, ks * 2 + c8A_half);
                uint32_t a16[4];
                ldsm4(a16, b0 + off);
#pragma unroll
                for (int nf = 0; nf < 4; nf++)
                    mma_h(acc[mf][nf], a16, &bh[nf * 2]);
            }
        }
    }
}

// ============================================================================
// k_scores_fused:
//   blocks [0, 1024):            scores GEMM (3-stage pipeline, tensor-bound)
//   blocks [1024, 1024+4064):    y fp32->fp16 conversion, MLP=8 fillers
//   blocks [1024+4064, +32):     out[:,0] = y[:,0], MLP=8
// ============================================================================
__global__ __launch_bounds__(256, 2) void k_scores_fused(
    const float* __restrict__ ba1, const float* __restrict__ wa2,
    const float* __restrict__ y, float* __restrict__ out)
{
    extern __shared__ char dyn[];
    const int bx = blockIdx.x;
    const int tid = threadIdx.x;

    if (bx >= 1024) {
        const int idx = bx - 1024;
        if (idx < 4064) {
            const int r0 = idx * 16;
            const int j = tid & 127;
            const int rs = tid >> 7;           // 0..1
            const float* src[8];
            int rr[8];
#pragma unroll
            for (int u = 0; u < 8; u++) {
                const int r = r0 + rs + 2 * u;
                rr[u] = r;
                const int b = r / 8128;
                const int rem = r - b * 8128;
                const int sp = rem >> 6, n = rem & 63;
                src[u] = y + ((((size_t)(b * Sn) + sp + 1) * Nn + n) << 9) + j * 4;
            }
            float4 v[8];
#pragma unroll
            for (int u = 0; u < 8; u++) v[u] = *(const float4*)src[u];
#pragma unroll
            for (int u = 0; u < 8; u++) {
                uint2 h;
                h.x = pkh(v[u].x, v[u].y); h.y = pkh(v[u].z, v[u].w);
                ((uint2*)g_y16)[(size_t)rr[u] * 128 + j] = h;
            }
        } else {
            const int base = (idx - 4064) * 2048 + tid;
            float4 v[8];
#pragma unroll
            for (int u = 0; u < 8; u++) {
                const int s = base + 256 * u;
                const int b = s >> 13, jj = s & 8191;
                v[u] = *(const float4*)(y + (size_t)b * Sn * Nn * Hd + (size_t)jj * 4);
            }
#pragma unroll
            for (int u = 0; u < 8; u++) {
                const int s = base + 256 * u;
                const int b = s >> 13, jj = s & 8191;
                *(float4*)(out + (size_t)b * Sn * Nn * Hd + (size_t)jj * 4) = v[u];
            }
        }
        return;
    }

    const uint32_t smu = (smem_u32(dyn) + 127) & ~127u;
    const int row0 = (bx & 255) * 128;
    const int gg = (bx >> 8) * 128;
    const int lid = tid & 31, wid = tid >> 5;
    const int wm = wid >> 2, wn = wid & 3;
    const int groupID = lid >> 2, tig = lid & 3;

    float acc[4][4][4];
#pragma unroll
    for (int a = 0; a < 4; a++)
#pragma unroll
        for (int b = 0; b < 4; b++)
#pragma unroll
            for (int c = 0; c < 4; c++) acc[a][b][c] = 0.f;

    hmma_loop3(g_x16 + ((size_t)row0 << 9), g_bs16 + ((size_t)gg << 9), smu, acc);

    const int colw = gg + wn * 32;
#pragma unroll
    for (int mf = 0; mf < 4; mf++) {
#pragma unroll
        for (int half = 0; half < 2; half++) {
            const int R = row0 + wm * 64 + mf * 16 + groupID + half * 8;
            float s = 0.f;
#pragma unroll
            for (int nf = 0; nf < 4; nf++) {
                const int g = colw + nf * 8 + tig * 2;
                float a0 = acc[mf][nf][half * 2 + 0];
                float a1 = acc[mf][nf][half * 2 + 1];
                s += tanh_fast(a0 + __ldg(ba1 + g))     * __ldg(wa2 + g);
                s += tanh_fast(a1 + __ldg(ba1 + g + 1)) * __ldg(wa2 + g + 1);
            }
            s += __shfl_xor_sync(0xffffffffu, s, 1);
            s += __shfl_xor_sync(0xffffffffu, s, 2);
            if (tig == 0)
                g_spart[((bx >> 8) * 4 + wn) * ROWS_X + R] = s;
        }
    }
}

// ============================================================================
// k_main_mma: pre = y@Wy^T + ci ; out = y16 + i_x*sigmoid(pre)
// ci/pooled rows staged in smem once per block (each element is shared by
// 64 n-rows; removes 64x-redundant epilogue LDGs from the latency path).
// grid (508, 4), 256 threads
// ============================================================================
__global__ __launch_bounds__(256, 2) void k_main_mma(float* __restrict__ out)
{
    extern __shared__ char dyn[];
    __shared__ float s_ci[2][128];
    __shared__ float s_ix[2][128];
    const uint32_t smu = (smem_u32(dyn) + 127) & ~127u;

    const int row0 = blockIdx.x * 128;
    const int gg = blockIdx.y * 128;
    const int tid = threadIdx.x;
    const int lid = tid & 31, wid = tid >> 5;
    const int wm = wid >> 2, wn = wid & 3;
    const int groupID = lid >> 2, tig = lid & 3;

    float acc[4][4][4];
#pragma unroll
    for (int a = 0; a < 4; a++)
#pragma unroll
        for (int b = 0; b < 4; b++)
#pragma unroll
            for (int c = 0; c < 4; c++) acc[a][b][c] = 0.f;

    hmma_loop3(g_y16 + ((size_t)row0 << 9), g_bm16 + ((size_t)gg << 9), smu, acc);

    // stage the 2 ci rows and 2 pooled rows this block needs (pair = b*127+sp)
    {
        const int pr = tid >> 7;            // 0..1
        const int cc = tid & 127;
        const int q = (row0 >> 6) + pr;     // pair index = b*127 + sp
        const int b = q / 127;
        const int sp = q - b * 127;
        s_ci[pr][cc] = g_ci[((size_t)q << 9) + gg + cc];
        s_ix[pr][cc] = g_pooled[(((size_t)(b * Sn) + sp) << 9) + gg + cc];
    }
    __syncthreads();

    const int colw = gg + wn * 32;
#pragma unroll
    for (int mf = 0; mf < 4; mf++) {
#pragma unroll
        for (int half = 0; half < 2; half++) {
            const int R = row0 + wm * 64 + mf * 16 + groupID + half * 8;
            const int pr = (R >> 6) - (row0 >> 6);     // 0 or 1
            const int b = R / 8128;
            const int rem = R - b * 8128;
            const int sp = rem >> 6, n = rem & 63;
            float* orow = out + ((((size_t)(b * Sn) + sp + 1) * Nn + n) << 9) + colw;
            const __half* yh = g_y16 + ((size_t)R << 9) + colw;
#pragma unroll
            for (int nf = 0; nf < 4; nf++) {
                const int c = nf * 8 + tig * 2;
                const int cl = wn * 32 + c;            // 0..127 within gg slice
                float a0 = acc[mf][nf][half * 2 + 0];
                float a1 = acc[mf][nf][half * 2 + 1];
                float2 ci2 = *(const float2*)&s_ci[pr][cl];
                float2 ix2 = *(const float2*)&s_ix[pr][cl];
                __half2 yh2 = *(const __half2*)(yh + c);
                float2 y2 = __half22float2(yh2);
                float2 o;
                o.x = y2.x + ix2.x * fsig(a0 + ci2.x);
                o.y = y2.y + ix2.y * fsig(a1 + ci2.y);
                *(float2*)(orow + c) = o;
            }
        }
    }
}

// ============================================================================
// k_ci_mma: ci = pooled @ Wi^T + bl      (HMMA, pooled fp16)
// A rows = b*128+s (1024 rows, s=127 rows unused). grid (8, 4), 256 threads.
// ============================================================================
__global__ __launch_bounds__(256, 2) void k_ci_mma(const float* __restrict__ bl)
{
    extern __shared__ char dyn[];
    const uint32_t smu = (smem_u32(dyn) + 127) & ~127u;

    const int row0 = blockIdx.x * 128;
    const int gg = blockIdx.y * 128;
    const int tid = threadIdx.x;
    const int lid = tid & 31, wid = tid >> 5;
    const int wm = wid >> 2, wn = wid & 3;
    const int groupID = lid >> 2, tig = lid & 3;

    float acc[4][4][4];
#pragma unroll
    for (int a = 0; a < 4; a++)
#pragma unroll
        for (int b = 0; b < 4; b++)
#pragma unroll
            for (int c = 0; c < 4; c++) acc[a][b][c] = 0.f;

    hmma_loop3(g_p16 + ((size_t)row0 << 9), g_bi16 + ((size_t)gg << 9), smu, acc);

    const int colw = gg + wn * 32;
#pragma unroll
    for (int mf = 0; mf < 4; mf++) {
#pragma unroll
        for (int half = 0; half < 2; half++) {
            const int R = row0 + wm * 64 + mf * 16 + groupID + half * 8;
            const int b = R >> 7, sp = R & 127;
            if (sp < 127) {
                float* crow = g_ci + (((size_t)(b * 127 + sp)) << 9) + colw;
#pragma unroll
                for (int nf = 0; nf < 4; nf++) {
                    const int c = nf * 8 + tig * 2;
                    float2 o;
                    o.x = acc[mf][nf][half * 2 + 0] + __ldg(bl + colw + c);
                    o.y = acc[mf][nf][half * 2 + 1] + __ldg(bl + colw + c + 1);
                    *(float2*)(crow + c) = o;
                }
            }
        }
    }
}

// ============================================================================
// k_pool: softmax over m + weighted pool, reading fp16 x
// ============================================================================
__global__ __launch_bounds__(128) void k_pool()
{
    const int bs = blockIdx.x;
    __shared__ float attn[32];
    const int tid = threadIdx.x;
    if (tid < 32) {
        float s = 0.f;
#pragma unroll
        for (int q = 0; q < NSLICE; q++) s += g_spart[q * ROWS_X + bs * Mn + tid];
        float mx = s;
#pragma unroll
        for (int o = 16; o > 0; o >>= 1)
            mx = fmaxf(mx, __shfl_xor_sync(0xffffffffu, mx, o));
        float e = expf(s - mx);
        float sum = e;
#pragma unroll
        for (int o = 16; o > 0; o >>= 1)
            sum += __shfl_xor_sync(0xffffffffu, sum, o);
        attn[tid] = e / sum;
    }
    __syncthreads();

    const int h0 = tid * 4;
    const __half* xb = g_x16 + (size_t)bs * Mn * Hd + h0;
    float s0 = 0.f, s1 = 0.f, s2 = 0.f, s3 = 0.f;
#pragma unroll
    for (int m = 0; m < Mn; m++) {
        uint2 d = *(const uint2*)(xb + (size_t)m * Hd);
        float2 lo = __half22float2(*reinterpret_cast<__half2*>(&d.x));
        float2 hi = __half22float2(*reinterpret_cast<__half2*>(&d.y));
        const float a = attn[m];
        s0 = fmaf(a, lo.x, s0);
        s1 = fmaf(a, lo.y, s1);
        s2 = fmaf(a, hi.x, s2);
        s3 = fmaf(a, hi.y, s3);
    }
    *(float4*)(g_pooled + (size_t)bs * Hd + h0) = make_float4(s0, s1, s2, s3);
    uint2 p;
    p.x = pkh(s0, s1); p.y = pkh(s2, s3);
    *(uint2*)(g_p16 + (size_t)bs * Hd + h0) = p;
}

extern "C" void kernel_launch(void* const* d_in, const int* in_sizes, int n_in,
                              void* d_out, int out_size)
{
    const float* x   = (const float*)d_in[0];
    const float* y   = (const float*)d_in[1];
    const float* Wa1 = (const float*)d_in[2];
    const float* ba1 = (const float*)d_in[3];
    const float* wa2 = (const float*)d_in[4];
    const float* Wl  = (const float*)d_in[5];
    const float* bl  = (const float*)d_in[6];
    float* out = (float*)d_out;

    cudaFuncSetAttribute(k_scores_fused, cudaFuncAttributeMaxDynamicSharedMemorySize, DSMEM);
    cudaFuncSetAttribute(k_main_mma,     cudaFuncAttributeMaxDynamicSharedMemorySize, DSMEM);
    cudaFuncSetAttribute(k_ci_mma,       cudaFuncAttributeMaxDynamicSharedMemorySize, DSMEM);

    k_cvt_xw<<<32768 + 512, 128>>>(x, Wa1, Wl);
    k_scores_fused<<<1024 + 4064 + 32, 256, DSMEM>>>(ba1, wa2, y, out);
    k_pool<<<Bn * Sn, 128>>>();
    k_ci_mma<<<dim3(8, 4), 256, DSMEM>>>(bl);
    k_main_mma<<<dim3(ROWS_Y / 128, 4), 256, DSMEM>>>(out);
}

// round 14
// speedup vs baseline: 1.4221x; 1.4221x over previous
#include <cuda_runtime.h>
#include <cuda_fp16.h>
#include <cstdint>

#define Hd 512
#define Bn 8
#define Sn 128
#define Mn 32
#define Nn 64

#define ROWS_Y  (Bn * (Sn - 1) * Nn)   // 65024 = 508*128
#define ROWS_X  (Bn * Sn * Mn)         // 32768 = 256*128
#define NSLICE  16

// ---------------- device scratch ----------------
__device__ float g_spart[NSLICE * ROWS_X];
__device__ float g_pooled[Bn * Sn * Hd];
__device__ float g_ci[Bn * (Sn - 1) * Hd];

__device__ __half g_x16[(size_t)ROWS_X * Hd];
__device__ __half g_y16[(size_t)ROWS_Y * Hd];
__device__ __half g_p16[(size_t)(Bn * Sn) * Hd];   // pooled fp16, row = b*128+s
__device__ __half g_bs16[Hd * Hd];   // scores B: fp16(Wa1^T) [g][k]
__device__ __half g_bm16[Hd * Hd];   // main B: fp16(Wy rows) [g][k]
__device__ __half g_bi16[Hd * Hd];   // ci B: fp16(Wi rows) [g][k]

// ---------------- helpers ----------------
__device__ __forceinline__ uint32_t smem_u32(const void* p) {
    uint32_t a;
    asm("{ .reg .u64 t; cvta.to.shared.u64 t, %1; cvt.u32.u64 %0, t; }" : "=r"(a) : "l"(p));
    return a;
}
__device__ __forceinline__ void cp16(uint32_t saddr, const void* gptr) {
    asm volatile("cp.async.cg.shared.global [%0], [%1], 16;" :: "r"(saddr), "l"(gptr));
}
__device__ __forceinline__ void ldsm4(uint32_t* r, uint32_t addr) {
    asm volatile("ldmatrix.sync.aligned.m8n8.x4.shared.b16 {%0,%1,%2,%3}, [%4];"
                 : "=r"(r[0]), "=r"(r[1]), "=r"(r[2]), "=r"(r[3]) : "r"(addr));
}
__device__ __forceinline__ void mma_h(float* c, const uint32_t* a, const uint32_t* b) {
    asm volatile(
        "mma.sync.aligned.m16n8k16.row.col.f32.f16.f16.f32 "
        "{%0,%1,%2,%3}, {%4,%5,%6,%7}, {%8,%9}, {%0,%1,%2,%3};"
        : "+f"(c[0]), "+f"(c[1]), "+f"(c[2]), "+f"(c[3])
        : "r"(a[0]), "r"(a[1]), "r"(a[2]), "r"(a[3]), "r"(b[0]), "r"(b[1]));
}
__device__ __forceinline__ float tanh_fast(float x) {
    float r;
    asm("tanh.approx.f32 %0, %1;" : "=f"(r) : "f"(x));
    return r;
}
// gate = sigmoid(x) = 0.5 + 0.5*tanh(0.5x)  (1 MUFU)
__device__ __forceinline__ float fsig(float x) {
    return fmaf(tanh_fast(0.5f * x), 0.5f, 0.5f);
}

__device__ __forceinline__ unsigned pkh(float a, float b) {
    __half2 t = __floats2half2_rn(a, b);
    return *reinterpret_cast<unsigned*>(&t);
}

// swizzled offset inside a [rows x 64 fp16] tile (128 B rows)
__device__ __forceinline__ uint32_t sw(int row, int c8) {
    return (uint32_t)(row * 128 + ((c8 ^ (row & 7)) << 4));
}

// ============================================================================
// k_cvt_xw: blocks [0, 32768) convert x; [32768, 33280) convert weights
// ============================================================================
__global__ __launch_bounds__(128) void k_cvt_xw(const float* __restrict__ x,
                                                const float* __restrict__ Wa1,
                                                const float* __restrict__ Wl) {
    const int t = threadIdx.x;
    if (blockIdx.x < 32768) {
        const int r = blockIdx.x;
        float4 v = *(const float4*)(x + ((size_t)r << 9) + t * 4);
        uint2 h;
        h.x = pkh(v.x, v.y); h.y = pkh(v.z, v.w);
        ((uint2*)g_x16)[(size_t)r * 128 + t] = h;
    } else {
        const int g = blockIdx.x - 32768;
        {   // main B: Wl row g, first Hd cols (Wy)
            float4 v = *(const float4*)(Wl + (size_t)g * 1024 + t * 4);
            uint2 h;
            h.x = pkh(v.x, v.y); h.y = pkh(v.z, v.w);
            ((uint2*)g_bm16)[(size_t)g * 128 + t] = h;
        }
        {   // ci B: Wl row g, cols [Hd, 2Hd) (Wi)
            float4 v = *(const float4*)(Wl + (size_t)g * 1024 + Hd + t * 4);
            uint2 h;
            h.x = pkh(v.x, v.y); h.y = pkh(v.z, v.w);
            ((uint2*)g_bi16)[(size_t)g * 128 + t] = h;
        }
        {   // scores B: Wa1^T row g
            int k0 = t * 4;
            float a = Wa1[(size_t)(k0 + 0) * Hd + g];
            float b = Wa1[(size_t)(k0 + 1) * Hd + g];
            float c = Wa1[(size_t)(k0 + 2) * Hd + g];
            float d = Wa1[(size_t)(k0 + 3) * Hd + g];
            uint2 h;
            h.x = pkh(a, b); h.y = pkh(c, d);
            ((uint2*)g_bs16)[(size_t)g * 128 + t] = h;
        }
    }
}

// ============================================================================
// 3-stage pipelined fp16 mainloop: block tile 128(M) x 128(N), K=512.
// Stage: A 16K | B 16K = 32 KB; 3 stages (96 KB/CTA), 2 CTAs/SM.
// 256 threads, warps 2(M) x 4(N), warp tile 64x32, fp32 accumulate.
// NOTE: caller may commit extra cp.async groups BEFORE calling; the
// wait_group bounds here remain correct (early groups drain first).
// ============================================================================
#define STG   32768
#define DSMEM (3 * STG + 128)

__device__ __forceinline__ void hmma_loop3(
    const __half* __restrict__ A16, const __half* __restrict__ B16,
    uint32_t smu, float acc[4][4][4])
{
    const int tid = threadIdx.x;
    const int lid = tid & 31, wid = tid >> 5;
    const int wm = wid >> 2, wn = wid & 3;

    int rowS[4], c8S[4];
    uint32_t soS[4];
#pragma unroll
    for (int i = 0; i < 4; i++) {
        int id = tid + 256 * i;
        rowS[i] = id >> 3; c8S[i] = id & 7;
        soS[i] = sw(rowS[i], c8S[i]);
    }

    const int rowA_base = wm * 64 + (lid & 15);
    const int c8A_half = lid >> 4;
    const int rowB_base = wn * 32 + ((lid >> 4) << 3) + (lid & 7);
    const int c8B_half = (lid >> 3) & 1;

    // prologue: chunks 0 and 1
#pragma unroll
    for (int p = 0; p < 2; p++) {
        const uint32_t bb = smu + p * STG;
        const int kk = p * 64;
#pragma unroll
        for (int i = 0; i < 4; i++) {
            const size_t go = (size_t)rowS[i] * Hd + kk + c8S[i] * 8;
            cp16(bb + soS[i], A16 + go);
            cp16(bb + 16384 + soS[i], B16 + go);
        }
        asm volatile("cp.async.commit_group;");
    }

#pragma unroll
    for (int it = 0; it < 8; ++it) {
        if (it == 7) asm volatile("cp.async.wait_group 0;" ::: "memory");
        else         asm volatile("cp.async.wait_group 1;" ::: "memory");
        __syncthreads();

        if (it < 6) {
            const uint32_t bb = smu + ((it + 2) % 3) * STG;
            const int kk = (it + 2) * 64;
#pragma unroll
            for (int i = 0; i < 4; i++) {
                const size_t go = (size_t)rowS[i] * Hd + kk + c8S[i] * 8;
                cp16(bb + soS[i], A16 + go);
                cp16(bb + 16384 + soS[i], B16 + go);
            }
            asm volatile("cp.async.commit_group;");
        }

        const uint32_t b0 = smu + (it % 3) * STG;
#pragma unroll
        for (int ks = 0; ks < 4; ks++) {
            uint32_t bh[8];
#pragma unroll
            for (int q = 0; q < 2; q++) {
                uint32_t off = sw(rowB_base + q * 16, ks * 2 + c8B_half);
                ldsm4(&bh[q * 4], b0 + 16384 + off);
            }
#pragma unroll
            for (int mf = 0; mf < 4; mf++) {
                uint32_t off = sw(rowA_base + mf * 16, ks * 2 + c8A_half);
                uint32_t a16[4];
                ldsm4(a16, b0 + off);
#pragma unroll
                for (int nf = 0; nf < 4; nf++)
                    mma_h(acc[mf][nf], a16, &bh[nf * 2]);
            }
        }
    }
}

// ============================================================================
// k_scores_fused:
//   blocks [0, 1024):            scores GEMM (3-stage pipeline, tensor-bound)
//   blocks [1024, 1024+4064):    y fp32->fp16 conversion, MLP=8 fillers
//   blocks [1024+4064, +32):     out[:,0] = y[:,0], MLP=8
// ============================================================================
__global__ __launch_bounds__(256, 2) void k_scores_fused(
    const float* __restrict__ ba1, const float* __restrict__ wa2,
    const float* __restrict__ y, float* __restrict__ out)
{
    extern __shared__ char dyn[];
    const int bx = blockIdx.x;
    const int tid = threadIdx.x;

    if (bx >= 1024) {
        const int idx = bx - 1024;
        if (idx < 4064) {
            const int r0 = idx * 16;
            const int j = tid & 127;
            const int rs = tid >> 7;           // 0..1
            const float* src[8];
            int rr[8];
#pragma unroll
            for (int u = 0; u < 8; u++) {
                const int r = r0 + rs + 2 * u;
                rr[u] = r;
                const int b = r / 8128;
                const int rem = r - b * 8128;
                const int sp = rem >> 6, n = rem & 63;
                src[u] = y + ((((size_t)(b * Sn) + sp + 1) * Nn + n) << 9) + j * 4;
            }
            float4 v[8];
#pragma unroll
            for (int u = 0; u < 8; u++) v[u] = *(const float4*)src[u];
#pragma unroll
            for (int u = 0; u < 8; u++) {
                uint2 h;
                h.x = pkh(v[u].x, v[u].y); h.y = pkh(v[u].z, v[u].w);
                ((uint2*)g_y16)[(size_t)rr[u] * 128 + j] = h;
            }
        } else {
            const int base = (idx - 4064) * 2048 + tid;
            float4 v[8];
#pragma unroll
            for (int u = 0; u < 8; u++) {
                const int s = base + 256 * u;
                const int b = s >> 13, jj = s & 8191;
                v[u] = *(const float4*)(y + (size_t)b * Sn * Nn * Hd + (size_t)jj * 4);
            }
#pragma unroll
            for (int u = 0; u < 8; u++) {
                const int s = base + 256 * u;
                const int b = s >> 13, jj = s & 8191;
                *(float4*)(out + (size_t)b * Sn * Nn * Hd + (size_t)jj * 4) = v[u];
            }
        }
        return;
    }

    const uint32_t smu = (smem_u32(dyn) + 127) & ~127u;
    const int row0 = (bx & 255) * 128;
    const int gg = (bx >> 8) * 128;
    const int lid = tid & 31, wid = tid >> 5;
    const int wm = wid >> 2, wn = wid & 3;
    const int groupID = lid >> 2, tig = lid & 3;

    float acc[4][4][4];
#pragma unroll
    for (int a = 0; a < 4; a++)
#pragma unroll
        for (int b = 0; b < 4; b++)
#pragma unroll
            for (int c = 0; c < 4; c++) acc[a][b][c] = 0.f;

    hmma_loop3(g_x16 + ((size_t)row0 << 9), g_bs16 + ((size_t)gg << 9), smu, acc);

    const int colw = gg + wn * 32;
#pragma unroll
    for (int mf = 0; mf < 4; mf++) {
#pragma unroll
        for (int half = 0; half < 2; half++) {
            const int R = row0 + wm * 64 + mf * 16 + groupID + half * 8;
            float s = 0.f;
#pragma unroll
            for (int nf = 0; nf < 4; nf++) {
                const int g = colw + nf * 8 + tig * 2;
                float a0 = acc[mf][nf][half * 2 + 0];
                float a1 = acc[mf][nf][half * 2 + 1];
                s += tanh_fast(a0 + __ldg(ba1 + g))     * __ldg(wa2 + g);
                s += tanh_fast(a1 + __ldg(ba1 + g + 1)) * __ldg(wa2 + g + 1);
            }
            s += __shfl_xor_sync(0xffffffffu, s, 1);
            s += __shfl_xor_sync(0xffffffffu, s, 2);
            if (tig == 0)
                g_spart[((bx >> 8) * 4 + wn) * ROWS_X + R] = s;
        }
    }
}

// ============================================================================
// k_main_mma: pre = y@Wy^T + ci ; out = y16 + i_x*sigmoid(pre)
// ci/pooled rows (2 KB) staged via cp.async BEFORE the mainloop prologue —
// the staging group drains by the first wait_group, hiding its latency under
// the whole K-loop. Epilogue reads are broadcast LDS hits.
// grid (508, 4), 256 threads
// ============================================================================
__global__ __launch_bounds__(256, 2) void k_main_mma(float* __restrict__ out)
{
    extern __shared__ char dyn[];
    __shared__ __align__(16) float s_ci[2][128];
    __shared__ __align__(16) float s_ix[2][128];
    const uint32_t smu = (smem_u32(dyn) + 127) & ~127u;

    const int row0 = blockIdx.x * 128;
    const int gg = blockIdx.y * 128;
    const int tid = threadIdx.x;
    const int lid = tid & 31, wid = tid >> 5;
    const int wm = wid >> 2, wn = wid & 3;
    const int groupID = lid >> 2, tig = lid & 3;

    // stage ci/pooled rows through the async pipe (group 0, drains first)
    if (tid < 128) {
        const int q0 = row0 >> 6;             // pair index base = b*127+sp
        if (tid < 64) {
            const int pr = tid >> 5, off = tid & 31;     // 32 x 16B per row
            cp16(smem_u32(&s_ci[0][0]) + tid * 16,
                 g_ci + (((size_t)(q0 + pr)) << 9) + gg + off * 4);
        } else {
            const int c2 = tid - 64;
            const int pr = c2 >> 5, off = c2 & 31;
            const int q = q0 + pr;
            const int b = q / 127;
            const int sp = q - b * 127;
            cp16(smem_u32(&s_ix[0][0]) + c2 * 16,
                 g_pooled + (((size_t)(b * Sn) + sp) << 9) + gg + off * 4);
        }
    }
    asm volatile("cp.async.commit_group;");

    float acc[4][4][4];
#pragma unroll
    for (int a = 0; a < 4; a++)
#pragma unroll
        for (int b = 0; b < 4; b++)
#pragma unroll
            for (int c = 0; c < 4; c++) acc[a][b][c] = 0.f;

    hmma_loop3(g_y16 + ((size_t)row0 << 9), g_bm16 + ((size_t)gg << 9), smu, acc);

    const int colw = gg + wn * 32;
#pragma unroll
    for (int mf = 0; mf < 4; mf++) {
#pragma unroll
        for (int half = 0; half < 2; half++) {
            const int R = row0 + wm * 64 + mf * 16 + groupID + half * 8;
            const int pr = (R >> 6) - (row0 >> 6);     // 0 or 1
            const int b = R / 8128;
            const int rem = R - b * 8128;
            const int sp = rem >> 6, n = rem & 63;
            float* orow = out + ((((size_t)(b * Sn) + sp + 1) * Nn + n) << 9) + colw;
            const __half* yh = g_y16 + ((size_t)R << 9) + colw;
#pragma unroll
            for (int nf = 0; nf < 4; nf++) {
                const int c = nf * 8 + tig * 2;
                const int cl = wn * 32 + c;            // 0..127 within gg slice
                float a0 = acc[mf][nf][half * 2 + 0];
                float a1 = acc[mf][nf][half * 2 + 1];
                float2 ci2 = *(const float2*)&s_ci[pr][cl];
                float2 ix2 = *(const float2*)&s_ix[pr][cl];
                __half2 yh2 = *(const __half2*)(yh + c);
                float2 y2 = __half22float2(yh2);
                float2 o;
                o.x = y2.x + ix2.x * fsig(a0 + ci2.x);
                o.y = y2.y + ix2.y * fsig(a1 + ci2.y);
                *(float2*)(orow + c) = o;
            }
        }
    }
}

// ============================================================================
// k_ci_mma: ci = pooled @ Wi^T + bl      (HMMA, pooled fp16)
// A rows = b*128+s (1024 rows, s=127 rows unused). grid (8, 4), 256 threads.
// ============================================================================
__global__ __launch_bounds__(256, 2) void k_ci_mma(const float* __restrict__ bl)
{
    extern __shared__ char dyn[];
    const uint32_t smu = (smem_u32(dyn) + 127) & ~127u;

    const int row0 = blockIdx.x * 128;
    const int gg = blockIdx.y * 128;
    const int tid = threadIdx.x;
    const int lid = tid & 31, wid = tid >> 5;
    const int wm = wid >> 2, wn = wid & 3;
    const int groupID = lid >> 2, tig = lid & 3;

    float acc[4][4][4];
#pragma unroll
    for (int a = 0; a < 4; a++)
#pragma unroll
        for (int b = 0; b < 4; b++)
#pragma unroll
            for (int c = 0; c < 4; c++) acc[a][b][c] = 0.f;

    hmma_loop3(g_p16 + ((size_t)row0 << 9), g_bi16 + ((size_t)gg << 9), smu, acc);

    const int colw = gg + wn * 32;
#pragma unroll
    for (int mf = 0; mf < 4; mf++) {
#pragma unroll
        for (int half = 0; half < 2; half++) {
            const int R = row0 + wm * 64 + mf * 16 + groupID + half * 8;
            const int b = R >> 7, sp = R & 127;
            if (sp < 127) {
                float* crow = g_ci + (((size_t)(b * 127 + sp)) << 9) + colw;
#pragma unroll
                for (int nf = 0; nf < 4; nf++) {
                    const int c = nf * 8 + tig * 2;
                    float2 o;
                    o.x = acc[mf][nf][half * 2 + 0] + __ldg(bl + colw + c);
                    o.y = acc[mf][nf][half * 2 + 1] + __ldg(bl + colw + c + 1);
                    *(float2*)(crow + c) = o;
                }
            }
        }
    }
}

// ============================================================================
// k_pool: softmax over m + weighted pool, reading fp16 x
// ============================================================================
__global__ __launch_bounds__(128) void k_pool()
{
    const int bs = blockIdx.x;
    __shared__ float attn[32];
    const int tid = threadIdx.x;
    if (tid < 32) {
        float s = 0.f;
#pragma unroll
        for (int q = 0; q < NSLICE; q++) s += g_spart[q * ROWS_X + bs * Mn + tid];
        float mx = s;
#pragma unroll
        for (int o = 16; o > 0; o >>= 1)
            mx = fmaxf(mx, __shfl_xor_sync(0xffffffffu, mx, o));
        float e = expf(s - mx);
        float sum = e;
#pragma unroll
        for (int o = 16; o > 0; o >>= 1)
            sum += __shfl_xor_sync(0xffffffffu, sum, o);
        attn[tid] = e / sum;
    }
    __syncthreads();

    const int h0 = tid * 4;
    const __half* xb = g_x16 + (size_t)bs * Mn * Hd + h0;
    float s0 = 0.f, s1 = 0.f, s2 = 0.f, s3 = 0.f;
#pragma unroll
    for (int m = 0; m < Mn; m++) {
        uint2 d = *(const uint2*)(xb + (size_t)m * Hd);
        float2 lo = __half22float2(*reinterpret_cast<__half2*>(&d.x));
        float2 hi = __half22float2(*reinterpret_cast<__half2*>(&d.y));
        const float a = attn[m];
        s0 = fmaf(a, lo.x, s0);
        s1 = fmaf(a, lo.y, s1);
        s2 = fmaf(a, hi.x, s2);
        s3 = fmaf(a, hi.y, s3);
    }
    *(float4*)(g_pooled + (size_t)bs * Hd + h0) = make_float4(s0, s1, s2, s3);
    uint2 p;
    p.x = pkh(s0, s1); p.y = pkh(s2, s3);
    *(uint2*)(g_p16 + (size_t)bs * Hd + h0) = p;
}

extern "C" void kernel_launch(void* const* d_in, const int* in_sizes, int n_in,
                              void* d_out, int out_size)
{
    const float* x   = (const float*)d_in[0];
    const float* y   = (const float*)d_in[1];
    const float* Wa1 = (const float*)d_in[2];
    const float* ba1 = (const float*)d_in[3];
    const float* wa2 = (const float*)d_in[4];
    const float* Wl  = (const float*)d_in[5];
    const float* bl  = (const float*)d_in[6];
    float* out = (float*)d_out;

    cudaFuncSetAttribute(k_scores_fused, cudaFuncAttributeMaxDynamicSharedMemorySize, DSMEM);
    cudaFuncSetAttribute(k_main_mma,     cudaFuncAttributeMaxDynamicSharedMemorySize, DSMEM);
    cudaFuncSetAttribute(k_ci_mma,       cudaFuncAttributeMaxDynamicSharedMemorySize, DSMEM);

    k_cvt_xw<<<32768 + 512, 128>>>(x, Wa1, Wl);
    k_scores_fused<<<1024 + 4064 + 32, 256, DSMEM>>>(ba1, wa2, y, out);
    k_pool<<<Bn * Sn, 128>>>();
    k_ci_mma<<<dim3(8, 4), 256, DSMEM>>>(bl);
    k_main_mma<<<dim3(ROWS_Y / 128, 4), 256, DSMEM>>>(out);
}

// round 15
// speedup vs baseline: 1.4545x; 1.0228x over previous
#include <cuda_runtime.h>
#include <cuda_fp16.h>
#include <cstdint>

#define Hd 512
#define Bn 8
#define Sn 128
#define Mn 32
#define Nn 64

#define ROWS_Y  (Bn * (Sn - 1) * Nn)   // 65024 = 508*128
#define ROWS_X  (Bn * Sn * Mn)         // 32768 = 256*128
#define NSLICE  16

// ---------------- device scratch ----------------
__device__ float g_spart[NSLICE * ROWS_X];
__device__ float g_pooled[Bn * Sn * Hd];
__device__ float g_ci[Bn * (Sn - 1) * Hd];

__device__ __half g_x16[(size_t)ROWS_X * Hd];
__device__ __half g_y16[(size_t)ROWS_Y * Hd];
__device__ __half g_p16[(size_t)(Bn * Sn) * Hd];   // pooled fp16, row = b*128+s
__device__ __half g_bs16[Hd * Hd];   // scores B: fp16(Wa1^T) [g][k]
__device__ __half g_bm16[Hd * Hd];   // main B: fp16(Wy rows) [g][k]
__device__ __half g_bi16[Hd * Hd];   // ci B: fp16(Wi rows) [g][k]

// ---------------- helpers ----------------
__device__ __forceinline__ uint32_t smem_u32(const void* p) {
    uint32_t a;
    asm("{ .reg .u64 t; cvta.to.shared.u64 t, %1; cvt.u32.u64 %0, t; }" : "=r"(a) : "l"(p));
    return a;
}
__device__ __forceinline__ void cp16(uint32_t saddr, const void* gptr) {
    asm volatile("cp.async.cg.shared.global [%0], [%1], 16;" :: "r"(saddr), "l"(gptr));
}
__device__ __forceinline__ void ldsm4(uint32_t* r, uint32_t addr) {
    asm volatile("ldmatrix.sync.aligned.m8n8.x4.shared.b16 {%0,%1,%2,%3}, [%4];"
                 : "=r"(r[0]), "=r"(r[1]), "=r"(r[2]), "=r"(r[3]) : "r"(addr));
}
__device__ __forceinline__ void mma_h(float* c, const uint32_t* a, const uint32_t* b) {
    asm volatile(
        "mma.sync.aligned.m16n8k16.row.col.f32.f16.f16.f32 "
        "{%0,%1,%2,%3}, {%4,%5,%6,%7}, {%8,%9}, {%0,%1,%2,%3};"
        : "+f"(c[0]), "+f"(c[1]), "+f"(c[2]), "+f"(c[3])
        : "r"(a[0]), "r"(a[1]), "r"(a[2]), "r"(a[3]), "r"(b[0]), "r"(b[1]));
}
__device__ __forceinline__ float tanh_fast(float x) {
    float r;
    asm("tanh.approx.f32 %0, %1;" : "=f"(r) : "f"(x));
    return r;
}
// gate = sigmoid(x) = 0.5 + 0.5*tanh(0.5x)  (1 MUFU)
__device__ __forceinline__ float fsig(float x) {
    return fmaf(tanh_fast(0.5f * x), 0.5f, 0.5f);
}

__device__ __forceinline__ unsigned pkh(float a, float b) {
    __half2 t = __floats2half2_rn(a, b);
    return *reinterpret_cast<unsigned*>(&t);
}

// swizzled offset inside a [rows x 64 fp16] tile (128 B rows)
__device__ __forceinline__ uint32_t sw(int row, int c8) {
    return (uint32_t)(row * 128 + ((c8 ^ (row & 7)) << 4));
}

// ============================================================================
// k_cvt_xw: blocks [0, 8192) convert x (4 rows/block, MLP=4);
//           blocks [8192, 8704) convert weights
// ============================================================================
__global__ __launch_bounds__(128) void k_cvt_xw(const float* __restrict__ x,
                                                const float* __restrict__ Wa1,
                                                const float* __restrict__ Wl) {
    const int t = threadIdx.x;
    if (blockIdx.x < 8192) {
        const int r0 = blockIdx.x * 4;
        float4 v[4];
#pragma unroll
        for (int u = 0; u < 4; u++)
            v[u] = *(const float4*)(x + ((size_t)(r0 + u) << 9) + t * 4);
#pragma unroll
        for (int u = 0; u < 4; u++) {
            uint2 h;
            h.x = pkh(v[u].x, v[u].y); h.y = pkh(v[u].z, v[u].w);
            ((uint2*)g_x16)[(size_t)(r0 + u) * 128 + t] = h;
        }
    } else {
        const int g = blockIdx.x - 8192;
        {   // main B: Wl row g, first Hd cols (Wy)
            float4 v = *(const float4*)(Wl + (size_t)g * 1024 + t * 4);
            uint2 h;
            h.x = pkh(v.x, v.y); h.y = pkh(v.z, v.w);
            ((uint2*)g_bm16)[(size_t)g * 128 + t] = h;
        }
        {   // ci B: Wl row g, cols [Hd, 2Hd) (Wi)
            float4 v = *(const float4*)(Wl + (size_t)g * 1024 + Hd + t * 4);
            uint2 h;
            h.x = pkh(v.x, v.y); h.y = pkh(v.z, v.w);
            ((uint2*)g_bi16)[(size_t)g * 128 + t] = h;
        }
        {   // scores B: Wa1^T row g
            int k0 = t * 4;
            float a = Wa1[(size_t)(k0 + 0) * Hd + g];
            float b = Wa1[(size_t)(k0 + 1) * Hd + g];
            float c = Wa1[(size_t)(k0 + 2) * Hd + g];
            float d = Wa1[(size_t)(k0 + 3) * Hd + g];
            uint2 h;
            h.x = pkh(a, b); h.y = pkh(c, d);
            ((uint2*)g_bs16)[(size_t)g * 128 + t] = h;
        }
    }
}

// ============================================================================
// 3-stage pipelined fp16 mainloop: block tile 128(M) x 128(N), K=512.
// Stage: A 16K | B 16K = 32 KB; 3 stages (96 KB/CTA), 2 CTAs/SM.
// 256 threads, warps 2(M) x 4(N), warp tile 64x32, fp32 accumulate.
// Caller may commit extra cp.async groups BEFORE calling (they drain first).
// ============================================================================
#define STG   32768
#define DSMEM (3 * STG + 128)

__device__ __forceinline__ void hmma_loop3(
    const __half* __restrict__ A16, const __half* __restrict__ B16,
    uint32_t smu, float acc[4][4][4])
{
    const int tid = threadIdx.x;
    const int lid = tid & 31, wid = tid >> 5;
    const int wm = wid >> 2, wn = wid & 3;

    int rowS[4], c8S[4];
    uint32_t soS[4];
#pragma unroll
    for (int i = 0; i < 4; i++) {
        int id = tid + 256 * i;
        rowS[i] = id >> 3; c8S[i] = id & 7;
        soS[i] = sw(rowS[i], c8S[i]);
    }

    const int rowA_base = wm * 64 + (lid & 15);
    const int c8A_half = lid >> 4;
    const int rowB_base = wn * 32 + ((lid >> 4) << 3) + (lid & 7);
    const int c8B_half = (lid >> 3) & 1;

    // prologue: chunks 0 and 1
#pragma unroll
    for (int p = 0; p < 2; p++) {
        const uint32_t bb = smu + p * STG;
        const int kk = p * 64;
#pragma unroll
        for (int i = 0; i < 4; i++) {
            const size_t go = (size_t)rowS[i] * Hd + kk + c8S[i] * 8;
            cp16(bb + soS[i], A16 + go);
            cp16(bb + 16384 + soS[i], B16 + go);
        }
        asm volatile("cp.async.commit_group;");
    }

#pragma unroll
    for (int it = 0; it < 8; ++it) {
        if (it == 7) asm volatile("cp.async.wait_group 0;" ::: "memory");
        else         asm volatile("cp.async.wait_group 1;" ::: "memory");
        __syncthreads();

        if (it < 6) {
            const uint32_t bb = smu + ((it + 2) % 3) * STG;
            const int kk = (it + 2) * 64;
#pragma unroll
            for (int i = 0; i < 4; i++) {
                const size_t go = (size_t)rowS[i] * Hd + kk + c8S[i] * 8;
                cp16(bb + soS[i], A16 + go);
                cp16(bb + 16384 + soS[i], B16 + go);
            }
            asm volatile("cp.async.commit_group;");
        }

        const uint32_t b0 = smu + (it % 3) * STG;
#pragma unroll
        for (int ks = 0; ks < 4; ks++) {
            uint32_t bh[8];
#pragma unroll
            for (int q = 0; q < 2; q++) {
                uint32_t off = sw(rowB_base + q * 16, ks * 2 + c8B_half);
                ldsm4(&bh[q * 4], b0 + 16384 + off);
            }
#pragma unroll
            for (int mf = 0; mf < 4; mf++) {
                uint32_t off = sw(rowA_base + mf * 16, ks * 2 + c8A_half);
                uint32_t a16[4];
                ldsm4(a16, b0 + off);
#pragma unroll
                for (int nf = 0; nf < 4; nf++)
                    mma_h(acc[mf][nf], a16, &bh[nf * 2]);
            }
        }
    }
}

// ============================================================================
// k_scores_fused:
//   blocks [0, 1024):  scores GEMM, gg varies FASTEST (bx&3) so the 4 blocks
//                      sharing an A tile are adjacent -> A reads hit L2.
//   blocks [1024, 1024+4064): y fp32->fp16 conversion, MLP=8 fillers
//   blocks [1024+4064, +32):  out[:,0] = y[:,0], MLP=8
// ============================================================================
__global__ __launch_bounds__(256, 2) void k_scores_fused(
    const float* __restrict__ ba1, const float* __restrict__ wa2,
    const float* __restrict__ y, float* __restrict__ out)
{
    extern __shared__ char dyn[];
    const int bx = blockIdx.x;
    const int tid = threadIdx.x;

    if (bx >= 1024) {
        const int idx = bx - 1024;
        if (idx < 4064) {
            const int r0 = idx * 16;
            const int j = tid & 127;
            const int rs = tid >> 7;           // 0..1
            const float* src[8];
            int rr[8];
#pragma unroll
            for (int u = 0; u < 8; u++) {
                const int r = r0 + rs + 2 * u;
                rr[u] = r;
                const int b = r / 8128;
                const int rem = r - b * 8128;
                const int sp = rem >> 6, n = rem & 63;
                src[u] = y + ((((size_t)(b * Sn) + sp + 1) * Nn + n) << 9) + j * 4;
            }
            float4 v[8];
#pragma unroll
            for (int u = 0; u < 8; u++) v[u] = *(const float4*)src[u];
#pragma unroll
            for (int u = 0; u < 8; u++) {
                uint2 h;
                h.x = pkh(v[u].x, v[u].y); h.y = pkh(v[u].z, v[u].w);
                ((uint2*)g_y16)[(size_t)rr[u] * 128 + j] = h;
            }
        } else {
            const int base = (idx - 4064) * 2048 + tid;
            float4 v[8];
#pragma unroll
            for (int u = 0; u < 8; u++) {
                const int s = base + 256 * u;
                const int b = s >> 13, jj = s & 8191;
                v[u] = *(const float4*)(y + (size_t)b * Sn * Nn * Hd + (size_t)jj * 4);
            }
#pragma unroll
            for (int u = 0; u < 8; u++) {
                const int s = base + 256 * u;
                const int b = s >> 13, jj = s & 8191;
                *(float4*)(out + (size_t)b * Sn * Nn * Hd + (size_t)jj * 4) = v[u];
            }
        }
        return;
    }

    const uint32_t smu = (smem_u32(dyn) + 127) & ~127u;
    const int ggi = bx & 3;                    // gg fastest -> A-tile L2 reuse
    const int row0 = (bx >> 2) * 128;
    const int gg = ggi * 128;
    const int lid = tid & 31, wid = tid >> 5;
    const int wm = wid >> 2, wn = wid & 3;
    const int groupID = lid >> 2, tig = lid & 3;

    float acc[4][4][4];
#pragma unroll
    for (int a = 0; a < 4; a++)
#pragma unroll
        for (int b = 0; b < 4; b++)
#pragma unroll
            for (int c = 0; c < 4; c++) acc[a][b][c] = 0.f;

    hmma_loop3(g_x16 + ((size_t)row0 << 9), g_bs16 + ((size_t)gg << 9), smu, acc);

    const int colw = gg + wn * 32;
#pragma unroll
    for (int mf = 0; mf < 4; mf++) {
#pragma unroll
        for (int half = 0; half < 2; half++) {
            const int R = row0 + wm * 64 + mf * 16 + groupID + half * 8;
            float s = 0.f;
#pragma unroll
            for (int nf = 0; nf < 4; nf++) {
                const int g = colw + nf * 8 + tig * 2;
                float a0 = acc[mf][nf][half * 2 + 0];
                float a1 = acc[mf][nf][half * 2 + 1];
                s += tanh_fast(a0 + __ldg(ba1 + g))     * __ldg(wa2 + g);
                s += tanh_fast(a1 + __ldg(ba1 + g + 1)) * __ldg(wa2 + g + 1);
            }
            s += __shfl_xor_sync(0xffffffffu, s, 1);
            s += __shfl_xor_sync(0xffffffffu, s, 2);
            if (tig == 0)
                g_spart[(ggi * 4 + wn) * ROWS_X + R] = s;
        }
    }
}

// ============================================================================
// k_main_mma: pre = y@Wy^T + ci ; out = y16 + i_x*sigmoid(pre)
// grid (4, 508): gg = blockIdx.x (FASTEST) -> the 4 blocks sharing an A tile
// are adjacent in issue order -> 3/4 of A reads are L2 hits.
// ci/pooled rows staged via cp.async group 0 (hidden under the K-loop).
// ============================================================================
__global__ __launch_bounds__(256, 2) void k_main_mma(float* __restrict__ out)
{
    extern __shared__ char dyn[];
    __shared__ __align__(16) float s_ci[2][128];
    __shared__ __align__(16) float s_ix[2][128];
    const uint32_t smu = (smem_u32(dyn) + 127) & ~127u;

    const int gg = blockIdx.x * 128;
    const int row0 = blockIdx.y * 128;
    const int tid = threadIdx.x;
    const int lid = tid & 31, wid = tid >> 5;
    const int wm = wid >> 2, wn = wid & 3;
    const int groupID = lid >> 2, tig = lid & 3;

    // stage ci/pooled rows through the async pipe (group 0, drains first)
    if (tid < 128) {
        const int q0 = row0 >> 6;             // pair index base = b*127+sp
        if (tid < 64) {
            const int pr = tid >> 5, off = tid & 31;     // 32 x 16B per row
            cp16(smem_u32(&s_ci[0][0]) + tid * 16,
                 g_ci + (((size_t)(q0 + pr)) << 9) + gg + off * 4);
        } else {
            const int c2 = tid - 64;
            const int pr = c2 >> 5, off = c2 & 31;
            const int q = q0 + pr;
            const int b = q / 127;
            const int sp = q - b * 127;
            cp16(smem_u32(&s_ix[0][0]) + c2 * 16,
                 g_pooled + (((size_t)(b * Sn) + sp) << 9) + gg + off * 4);
        }
    }
    asm volatile("cp.async.commit_group;");

    float acc[4][4][4];
#pragma unroll
    for (int a = 0; a < 4; a++)
#pragma unroll
        for (int b = 0; b < 4; b++)
#pragma unroll
            for (int c = 0; c < 4; c++) acc[a][b][c] = 0.f;

    hmma_loop3(g_y16 + ((size_t)row0 << 9), g_bm16 + ((size_t)gg << 9), smu, acc);

    const int colw = gg + wn * 32;
#pragma unroll
    for (int mf = 0; mf < 4; mf++) {
#pragma unroll
        for (int half = 0; half < 2; half++) {
            const int R = row0 + wm * 64 + mf * 16 + groupID + half * 8;
            const int pr = (R >> 6) - (row0 >> 6);     // 0 or 1
            const int b = R / 8128;
            const int rem = R - b * 8128;
            const int sp = rem >> 6, n = rem & 63;
            float* orow = out + ((((size_t)(b * Sn) + sp + 1) * Nn + n) << 9) + colw;
            const __half* yh = g_y16 + ((size_t)R << 9) + colw;
#pragma unroll
            for (int nf = 0; nf < 4; nf++) {
                const int c = nf * 8 + tig * 2;
                const int cl = wn * 32 + c;            // 0..127 within gg slice
                float a0 = acc[mf][nf][half * 2 + 0];
                float a1 = acc[mf][nf][half * 2 + 1];
                float2 ci2 = *(const float2*)&s_ci[pr][cl];
                float2 ix2 = *(const float2*)&s_ix[pr][cl];
                __half2 yh2 = *(const __half2*)(yh + c);
                float2 y2 = __half22float2(yh2);
                float2 o;
                o.x = y2.x + ix2.x * fsig(a0 + ci2.x);
                o.y = y2.y + ix2.y * fsig(a1 + ci2.y);
                *(float2*)(orow + c) = o;
            }
        }
    }
}

// ============================================================================
// k_ci_mma: ci = pooled @ Wi^T + bl      (HMMA, pooled fp16)
// A rows = b*128+s (1024 rows, s=127 rows unused). grid (8, 4), 256 threads.
// ============================================================================
__global__ __launch_bounds__(256, 2) void k_ci_mma(const float* __restrict__ bl)
{
    extern __shared__ char dyn[];
    const uint32_t smu = (smem_u32(dyn) + 127) & ~127u;

    const int row0 = blockIdx.x * 128;
    const int gg = blockIdx.y * 128;
    const int tid = threadIdx.x;
    const int lid = tid & 31, wid = tid >> 5;
    const int wm = wid >> 2, wn = wid & 3;
    const int groupID = lid >> 2, tig = lid & 3;

    float acc[4][4][4];
#pragma unroll
    for (int a = 0; a < 4; a++)
#pragma unroll
        for (int b = 0; b < 4; b++)
#pragma unroll
            for (int c = 0; c < 4; c++) acc[a][b][c] = 0.f;

    hmma_loop3(g_p16 + ((size_t)row0 << 9), g_bi16 + ((size_t)gg << 9), smu, acc);

    const int colw = gg + wn * 32;
#pragma unroll
    for (int mf = 0; mf < 4; mf++) {
#pragma unroll
        for (int half = 0; half < 2; half++) {
            const int R = row0 + wm * 64 + mf * 16 + groupID + half * 8;
            const int b = R >> 7, sp = R & 127;
            if (sp < 127) {
                float* crow = g_ci + (((size_t)(b * 127 + sp)) << 9) + colw;
#pragma unroll
                for (int nf = 0; nf < 4; nf++) {
                    const int c = nf * 8 + tig * 2;
                    float2 o;
                    o.x = acc[mf][nf][half * 2 + 0] + __ldg(bl + colw + c);
                    o.y = acc[mf][nf][half * 2 + 1] + __ldg(bl + colw + c + 1);
                    *(float2*)(crow + c) = o;
                }
            }
        }
    }
}

// ============================================================================
// k_pool: softmax over m + weighted pool, reading fp16 x
// ============================================================================
__global__ __launch_bounds__(128) void k_pool()
{
    const int bs = blockIdx.x;
    __shared__ float attn[32];
    const int tid = threadIdx.x;
    if (tid < 32) {
        float s = 0.f;
#pragma unroll
        for (int q = 0; q < NSLICE; q++) s += g_spart[q * ROWS_X + bs * Mn + tid];
        float mx = s;
#pragma unroll
        for (int o = 16; o > 0; o >>= 1)
            mx = fmaxf(mx, __shfl_xor_sync(0xffffffffu, mx, o));
        float e = expf(s - mx);
        float sum = e;
#pragma unroll
        for (int o = 16; o > 0; o >>= 1)
            sum += __shfl_xor_sync(0xffffffffu, sum, o);
        attn[tid] = e / sum;
    }
    __syncthreads();

    const int h0 = tid * 4;
    const __half* xb = g_x16 + (size_t)bs * Mn * Hd + h0;
    float s0 = 0.f, s1 = 0.f, s2 = 0.f, s3 = 0.f;
#pragma unroll
    for (int m = 0; m < Mn; m++) {
        uint2 d = *(const uint2*)(xb + (size_t)m * Hd);
        float2 lo = __half22float2(*reinterpret_cast<__half2*>(&d.x));
        float2 hi = __half22float2(*reinterpret_cast<__half2*>(&d.y));
        const float a = attn[m];
        s0 = fmaf(a, lo.x, s0);
        s1 = fmaf(a, lo.y, s1);
        s2 = fmaf(a, hi.x, s2);
        s3 = fmaf(a, hi.y, s3);
    }
    *(float4*)(g_pooled + (size_t)bs * Hd + h0) = make_float4(s0, s1, s2, s3);
    uint2 p;
    p.x = pkh(s0, s1); p.y = pkh(s2, s3);
    *(uint2*)(g_p16 + (size_t)bs * Hd + h0) = p;
}

extern "C" void kernel_launch(void* const* d_in, const int* in_sizes, int n_in,
                              void* d_out, int out_size)
{
    const float* x   = (const float*)d_in[0];
    const float* y   = (const float*)d_in[1];
    const float* Wa1 = (const float*)d_in[2];
    const float* ba1 = (const float*)d_in[3];
    const float* wa2 = (const float*)d_in[4];
    const float* Wl  = (const float*)d_in[5];
    const float* bl  = (const float*)d_in[6];
    float* out = (float*)d_out;

    cudaFuncSetAttribute(k_scores_fused, cudaFuncAttributeMaxDynamicSharedMemorySize, DSMEM);
    cudaFuncSetAttribute(k_main_mma,     cudaFuncAttributeMaxDynamicSharedMemorySize, DSMEM);
    cudaFuncSetAttribute(k_ci_mma,       cudaFuncAttributeMaxDynamicSharedMemorySize, DSMEM);

    k_cvt_xw<<<8192 + 512, 128>>>(x, Wa1, Wl);
    k_scores_fused<<<1024 + 4064 + 32, 256, DSMEM>>>(ba1, wa2, y, out);
    k_pool<<<Bn * Sn, 128>>>();
    k_ci_mma<<<dim3(8, 4), 256, DSMEM>>>(bl);
    k_main_mma<<<dim3(4, ROWS_Y / 128), 256, DSMEM>>>(out);
}